// round 1
// baseline (speedup 1.0000x reference)
#include <cuda_runtime.h>
#include <cstdint>

#define PEPS 1e-5f
#define DIMS 64

// Accumulators: 0 = sum softplus(pos), 1 = sum softplus(-neg), 2 = sum 1/(rank+1)
__device__ double g_acc[3];
// Scratch for edge scores: pos edges [0, E_pos), neg edges [E_pos, E_pos+E_neg)
__device__ float g_scores[3200000];

__global__ void init_acc_kernel() {
    g_acc[0] = 0.0; g_acc[1] = 0.0; g_acc[2] = 0.0;
}

// ---------------------------------------------------------------------------
// Phase A: Poincare dist^2 per edge. 8 lanes per edge (4 edges per warp).
// Each lane loads 2x float4 per row (contiguous 128B per octet per LDG ->
// minimal L1tex wavefronts: 4 per edge). 3 partial sums reduced with 9
// shfl_xor per 4 edges.
// ---------------------------------------------------------------------------
__global__ __launch_bounds__(256) void score_kernel(
    const float* __restrict__ h,
    const int* __restrict__ pos_src, const int* __restrict__ pos_dst,
    const int* __restrict__ neg_src, const int* __restrict__ neg_dst,
    int E_pos, int E_tot)
{
    const int lane   = threadIdx.x & 31;
    const int oct    = lane >> 3;          // which edge within warp (0..3)
    const int t      = lane & 7;           // lane within octet (0..7)
    const int warpId = (blockIdx.x * blockDim.x + threadIdx.x) >> 5;

    int e = warpId * 4 + oct;
    bool valid = (e < E_tot);
    int eg = valid ? e : 0;                // dummy work for tail (keeps shfl masks full)

    int a, b;
    if (eg < E_pos) { a = pos_src[eg]; b = pos_dst[eg]; }
    else            { a = neg_src[eg - E_pos]; b = neg_dst[eg - E_pos]; }

    const float4* pu = (const float4*)(h + (size_t)a * DIMS);
    const float4* pv = (const float4*)(h + (size_t)b * DIMS);

    // floats [4t..4t+3] and [32+4t..32+4t+3]: first/second 128B line of the row
    float4 u0 = pu[t], u1 = pu[t + 8];
    float4 v0 = pv[t], v1 = pv[t + 8];

    float du, nu, nv, d;
    d  = u0.x - v0.x; du = d * d;            nu = u0.x * u0.x;            nv = v0.x * v0.x;
    d  = u0.y - v0.y; du = fmaf(d, d, du);   nu = fmaf(u0.y, u0.y, nu);   nv = fmaf(v0.y, v0.y, nv);
    d  = u0.z - v0.z; du = fmaf(d, d, du);   nu = fmaf(u0.z, u0.z, nu);   nv = fmaf(v0.z, v0.z, nv);
    d  = u0.w - v0.w; du = fmaf(d, d, du);   nu = fmaf(u0.w, u0.w, nu);   nv = fmaf(v0.w, v0.w, nv);
    d  = u1.x - v1.x; du = fmaf(d, d, du);   nu = fmaf(u1.x, u1.x, nu);   nv = fmaf(v1.x, v1.x, nv);
    d  = u1.y - v1.y; du = fmaf(d, d, du);   nu = fmaf(u1.y, u1.y, nu);   nv = fmaf(v1.y, v1.y, nv);
    d  = u1.z - v1.z; du = fmaf(d, d, du);   nu = fmaf(u1.z, u1.z, nu);   nv = fmaf(v1.z, v1.z, nv);
    d  = u1.w - v1.w; du = fmaf(d, d, du);   nu = fmaf(u1.w, u1.w, nu);   nv = fmaf(v1.w, v1.w, nv);

    // reduce within octet (xor offsets < 8 never cross octets)
    #pragma unroll
    for (int o = 4; o > 0; o >>= 1) {
        du += __shfl_xor_sync(0xffffffffu, du, o);
        nu += __shfl_xor_sync(0xffffffffu, nu, o);
        nv += __shfl_xor_sync(0xffffffffu, nv, o);
    }

    float alpha = fmaxf(1.0f - nu, PEPS);
    float beta  = fmaxf(1.0f - nv, PEPS);
    float gam   = fmaxf(1.0f + __fdividef(2.0f * du, alpha * beta), 1.0f + PEPS);
    float ac    = __logf(gam + __fsqrt_rn(fmaf(gam, gam, -1.0f)));
    float sc    = ac * ac;

    if (valid && t == 0) g_scores[e] = sc;
}

// ---------------------------------------------------------------------------
// Phase B: per positive-edge group: softplus terms + MRR rank, block-reduced,
// one atomicAdd(double) per block per accumulator.
// ---------------------------------------------------------------------------
__device__ __forceinline__ float softplus_stable(float x) {
    return fmaxf(x, 0.0f) + log1pf(__expf(-fabsf(x)));
}

__device__ __forceinline__ float warp_sum(float v) {
    #pragma unroll
    for (int o = 16; o > 0; o >>= 1) v += __shfl_xor_sync(0xffffffffu, v, o);
    return v;
}

__global__ __launch_bounds__(256) void reduce_kernel(int E_pos, int nn)
{
    int i = blockIdx.x * blockDim.x + threadIdx.x;

    float sp_pos = 0.0f, sp_neg = 0.0f, mrr = 0.0f;
    if (i < E_pos) {
        float psc = g_scores[i];
        sp_pos = softplus_stable(psc);
        const float* nsc = g_scores + E_pos + (size_t)i * nn;
        int rank = 0;
        #pragma unroll 5
        for (int k = 0; k < nn; k++) {
            float v = nsc[k];
            sp_neg += softplus_stable(-v);
            rank += (v < psc) ? 1 : 0;   // neg_logit > pos_logit  <=>  neg_score < pos_score
        }
        mrr = 1.0f / (float)(rank + 1);
    }

    sp_pos = warp_sum(sp_pos);
    sp_neg = warp_sum(sp_neg);
    mrr    = warp_sum(mrr);

    __shared__ float sh[3][8];
    int wid = threadIdx.x >> 5;
    int lid = threadIdx.x & 31;
    if (lid == 0) { sh[0][wid] = sp_pos; sh[1][wid] = sp_neg; sh[2][wid] = mrr; }
    __syncthreads();

    if (threadIdx.x == 0) {
        float s0 = 0.f, s1 = 0.f, s2 = 0.f;
        #pragma unroll
        for (int w = 0; w < 8; w++) { s0 += sh[0][w]; s1 += sh[1][w]; s2 += sh[2][w]; }
        atomicAdd(&g_acc[0], (double)s0);
        atomicAdd(&g_acc[1], (double)s1);
        atomicAdd(&g_acc[2], (double)s2);
    }
}

__global__ void finalize_kernel(float* __restrict__ out, double invEp, double invEn)
{
    out[0] = (float)(g_acc[0] * invEp + g_acc[1] * invEn);
    out[1] = (float)(g_acc[2] * invEp);
}

extern "C" void kernel_launch(void* const* d_in, const int* in_sizes, int n_in,
                              void* d_out, int out_size)
{
    const float* h       = (const float*)d_in[0];
    const int*   pos_src = (const int*)d_in[1];
    const int*   pos_dst = (const int*)d_in[2];
    const int*   neg_src = (const int*)d_in[3];
    const int*   neg_dst = (const int*)d_in[4];

    const int E_pos = in_sizes[1];
    const int E_neg = in_sizes[3];
    const int nn    = E_neg / E_pos;
    const int E_tot = E_pos + E_neg;

    init_acc_kernel<<<1, 1>>>();

    // 4 edges per warp, 8 warps per block -> 32 edges per block
    int blocksA = (E_tot + 31) / 32;
    score_kernel<<<blocksA, 256>>>(h, pos_src, pos_dst, neg_src, neg_dst, E_pos, E_tot);

    int blocksB = (E_pos + 255) / 256;
    reduce_kernel<<<blocksB, 256>>>(E_pos, nn);

    finalize_kernel<<<1, 1>>>((float*)d_out, 1.0 / (double)E_pos, 1.0 / (double)E_neg);
}

// round 2
// speedup vs baseline: 1.2712x; 1.2712x over previous
#include <cuda_runtime.h>
#include <cstdint>

#define PEPS 1e-5f
#define DIMS 64
#define NSLOTS 32

// 32 accumulator slots x {sp_pos, sp_neg, mrr, pad} to de-serialize L2 atomics.
__device__ double g_accs[NSLOTS][4];

__global__ void init_acc_kernel() {
    int i = threadIdx.x;
    if (i < NSLOTS * 4) ((double*)g_accs)[i] = 0.0;
}

__device__ __forceinline__ float softplus_stable(float x) {
    return fmaxf(x, 0.0f) + log1pf(__expf(-fabsf(x)));
}

// ---------------------------------------------------------------------------
// Fused kernel: octet (8 lanes) <-> one positive group (1 pos + NN neg edges).
// Per edge: each lane loads 2x float4 (contiguous 128B per octet per LDG ->
// 4 L1tex wavefronts/edge, minimal). The xor-shuffle reduction leaves the
// score in ALL octet lanes, so all NN+1 group scores live in registers and
// softplus/rank/MRR are computed with zero scratch traffic.
// ---------------------------------------------------------------------------
template<int NN>
__global__ __launch_bounds__(256) void fused_kernel(
    const float* __restrict__ h,
    const int* __restrict__ pos_src, const int* __restrict__ pos_dst,
    const int* __restrict__ neg_src, const int* __restrict__ neg_dst,
    int E_pos)
{
    const int lane = threadIdx.x & 31;
    const int oct  = lane >> 3;            // group within warp (0..3)
    const int t    = lane & 7;             // lane within octet (0..7)
    const int warpId = (blockIdx.x * blockDim.x + threadIdx.x) >> 5;

    const int g = warpId * 4 + oct;
    const bool valid = (g < E_pos);
    const int gg = valid ? g : 0;          // dummy work for tail; keeps shfl masks full

    float s[NN + 1];

    #pragma unroll
    for (int k = 0; k <= NN; k++) {
        int a, b;
        if (k == 0) { a = pos_src[gg];                    b = pos_dst[gg]; }
        else        { a = neg_src[(size_t)gg * NN + k-1]; b = neg_dst[(size_t)gg * NN + k-1]; }

        const float4* pu = (const float4*)(h + (size_t)a * DIMS);
        const float4* pv = (const float4*)(h + (size_t)b * DIMS);
        float4 u0 = pu[t], u1 = pu[t + 8];
        float4 v0 = pv[t], v1 = pv[t + 8];

        float du, nu, nv, d;
        d = u0.x - v0.x; du = d * d;          nu = u0.x * u0.x;          nv = v0.x * v0.x;
        d = u0.y - v0.y; du = fmaf(d, d, du); nu = fmaf(u0.y, u0.y, nu); nv = fmaf(v0.y, v0.y, nv);
        d = u0.z - v0.z; du = fmaf(d, d, du); nu = fmaf(u0.z, u0.z, nu); nv = fmaf(v0.z, v0.z, nv);
        d = u0.w - v0.w; du = fmaf(d, d, du); nu = fmaf(u0.w, u0.w, nu); nv = fmaf(v0.w, v0.w, nv);
        d = u1.x - v1.x; du = fmaf(d, d, du); nu = fmaf(u1.x, u1.x, nu); nv = fmaf(v1.x, v1.x, nv);
        d = u1.y - v1.y; du = fmaf(d, d, du); nu = fmaf(u1.y, u1.y, nu); nv = fmaf(v1.y, v1.y, nv);
        d = u1.z - v1.z; du = fmaf(d, d, du); nu = fmaf(u1.z, u1.z, nu); nv = fmaf(v1.z, v1.z, nv);
        d = u1.w - v1.w; du = fmaf(d, d, du); nu = fmaf(u1.w, u1.w, nu); nv = fmaf(v1.w, v1.w, nv);

        // octet-wide reduce (xor offsets < 8 never cross octets); result in ALL lanes
        #pragma unroll
        for (int o = 4; o > 0; o >>= 1) {
            du += __shfl_xor_sync(0xffffffffu, du, o);
            nu += __shfl_xor_sync(0xffffffffu, nu, o);
            nv += __shfl_xor_sync(0xffffffffu, nv, o);
        }

        float alpha = fmaxf(1.0f - nu, PEPS);
        float beta  = fmaxf(1.0f - nv, PEPS);
        float gam   = fmaxf(1.0f + __fdividef(2.0f * du, alpha * beta), 1.0f + PEPS);
        float ac    = __logf(gam + __fsqrt_rn(fmaf(gam, gam, -1.0f)));
        s[k] = ac * ac;
    }

    // group-local epilogue (identical in all octet lanes; only t==0 contributes)
    float psc = s[0];
    float sp_pos = softplus_stable(psc);
    float sp_neg = 0.0f;
    int rank = 0;
    #pragma unroll
    for (int k = 1; k <= NN; k++) {
        sp_neg += softplus_stable(-s[k]);
        rank += (s[k] < psc) ? 1 : 0;      // neg_logit > pos_logit <=> neg_score < pos_score
    }
    float mrr = 1.0f / (float)(rank + 1);

    if (!valid || t != 0) { sp_pos = 0.0f; sp_neg = 0.0f; mrr = 0.0f; }

    // warp reduce
    #pragma unroll
    for (int o = 16; o > 0; o >>= 1) {
        sp_pos += __shfl_xor_sync(0xffffffffu, sp_pos, o);
        sp_neg += __shfl_xor_sync(0xffffffffu, sp_neg, o);
        mrr    += __shfl_xor_sync(0xffffffffu, mrr, o);
    }

    __shared__ float sh[3][8];
    const int wid = threadIdx.x >> 5;
    if (lane == 0) { sh[0][wid] = sp_pos; sh[1][wid] = sp_neg; sh[2][wid] = mrr; }
    __syncthreads();

    if (threadIdx.x == 0) {
        float s0 = 0.f, s1 = 0.f, s2 = 0.f;
        #pragma unroll
        for (int w = 0; w < 8; w++) { s0 += sh[0][w]; s1 += sh[1][w]; s2 += sh[2][w]; }
        double* slot = g_accs[blockIdx.x & (NSLOTS - 1)];
        atomicAdd(&slot[0], (double)s0);
        atomicAdd(&slot[1], (double)s1);
        atomicAdd(&slot[2], (double)s2);
    }
}

__global__ void finalize_kernel(float* __restrict__ out, double invEp, double invEn)
{
    double a0 = 0.0, a1 = 0.0, a2 = 0.0;
    #pragma unroll
    for (int i = 0; i < NSLOTS; i++) {
        a0 += g_accs[i][0]; a1 += g_accs[i][1]; a2 += g_accs[i][2];
    }
    out[0] = (float)(a0 * invEp + a1 * invEn);
    out[1] = (float)(a2 * invEp);
}

extern "C" void kernel_launch(void* const* d_in, const int* in_sizes, int n_in,
                              void* d_out, int out_size)
{
    const float* h       = (const float*)d_in[0];
    const int*   pos_src = (const int*)d_in[1];
    const int*   pos_dst = (const int*)d_in[2];
    const int*   neg_src = (const int*)d_in[3];
    const int*   neg_dst = (const int*)d_in[4];

    const int E_pos = in_sizes[1];
    const int E_neg = in_sizes[3];
    const int nn    = E_neg / E_pos;

    init_acc_kernel<<<1, 128>>>();

    // 4 groups per warp, 8 warps per block -> 32 groups per block
    int blocks = (E_pos + 31) / 32;
    if (nn == 5) {
        fused_kernel<5><<<blocks, 256>>>(h, pos_src, pos_dst, neg_src, neg_dst, E_pos);
    } else if (nn == 1) {
        fused_kernel<1><<<blocks, 256>>>(h, pos_src, pos_dst, neg_src, neg_dst, E_pos);
    } else if (nn == 2) {
        fused_kernel<2><<<blocks, 256>>>(h, pos_src, pos_dst, neg_src, neg_dst, E_pos);
    } else if (nn == 4) {
        fused_kernel<4><<<blocks, 256>>>(h, pos_src, pos_dst, neg_src, neg_dst, E_pos);
    } else if (nn == 8) {
        fused_kernel<8><<<blocks, 256>>>(h, pos_src, pos_dst, neg_src, neg_dst, E_pos);
    } else {
        fused_kernel<10><<<blocks, 256>>>(h, pos_src, pos_dst, neg_src, neg_dst, E_pos);
    }

    finalize_kernel<<<1, 1>>>((float*)d_out, 1.0 / (double)E_pos, 1.0 / (double)E_neg);
}